// round 5
// baseline (speedup 1.0000x reference)
#include <cuda_runtime.h>
#include <cuda_fp16.h>
#include <cstring>

#define NN 100000
#define EE 400000
#define D4 64          // 256 floats = 64 float4 per row
#define SS 10000
#define NT 98          // ceil(NN/1024) scan tiles per side
#define FILL_BLOCKS 3125          // (2*EE+255)/256
#define SCALE_BLOCKS 25000        // 2*NN*32 uint4 / 256

// ---------------- static scratch (no runtime allocation) ----------------
// NOTE: g_deg is zero-initialized at module load and re-zeroed at the END of
// each kernel_launch (in k_seed), so every call starts from zeros.
__device__ int    g_deg[2][NN];
__device__ int    g_cursor[2][NN];
__device__ int    g_rowptr[2][NN + 1];
__device__ int    g_adj[2][2 * EE];
__device__ float  g_dinv[2][NN];
__device__ int    g_tilesum[2][NT];
__device__ uint4  g_h0[2][(size_t)NN * 32];   // fp16 node table (512B/row), layer-1 input
__device__ uint4  g_h1[2][(size_t)NN * 32];   // fp16 node table, layer-2 input

// ---------------- half2 <-> float helpers ----------------
__device__ __forceinline__ float2 u2f(unsigned int u) {
    __half2 h; memcpy(&h, &u, 4); return __half22float2(h);
}
__device__ __forceinline__ unsigned int f2u(float a, float b) {
    __half2 h = __floats2half2_rn(a, b); unsigned int u; memcpy(&u, &h, 4); return u;
}
__device__ __forceinline__ void unpack_add8(float* a, uint4 v) {
    float2 f;
    f = u2f(v.x); a[0] += f.x; a[1] += f.y;
    f = u2f(v.y); a[2] += f.x; a[3] += f.y;
    f = u2f(v.z); a[4] += f.x; a[5] += f.y;
    f = u2f(v.w); a[6] += f.x; a[7] += f.y;
}

// ---------------- setup kernels ----------------
__global__ void k_count(const int2* __restrict__ esr, const int2* __restrict__ etg) {
    int i = blockIdx.x * 256 + threadIdx.x;
    if (i >= 2 * EE) return;
    int side = i >= EE;
    int j = i - side * EE;
    int2 ab = side ? etg[j] : esr[j];
    atomicAdd(&g_deg[side][ab.x], 1);   // no return use -> RED
    atomicAdd(&g_deg[side][ab.y], 1);
}

// stage 1: per-tile (1024 elems) degree sums
__global__ void k_s1() {
    __shared__ int ws[8];
    int b = blockIdx.x;
    int side = b >= NT;
    int t = b - side * NT;
    int tid = threadIdx.x;
    int base = t * 1024 + tid * 4;
    int s = 0;
    #pragma unroll
    for (int k = 0; k < 4; k++) {
        int i = base + k;
        if (i < NN) s += g_deg[side][i];
    }
    #pragma unroll
    for (int off = 16; off; off >>= 1) s += __shfl_xor_sync(0xffffffffu, s, off);
    if ((tid & 31) == 0) ws[tid >> 5] = s;
    __syncthreads();
    if (tid == 0) {
        int tot = 0;
        #pragma unroll
        for (int w = 0; w < 8; w++) tot += ws[w];
        g_tilesum[side][t] = tot;
    }
}

// stage 2+3 fused: each block warp-reduces tile sums before it, then does the
// in-tile exclusive scan -> rowptr / cursor / dinv
__global__ void k_s3() {
    __shared__ int ws[8];
    __shared__ int s_off;
    int b = blockIdx.x;
    int side = b >= NT;
    int t = b - side * NT;
    int tid = threadIdx.x, lane = tid & 31, wid = tid >> 5;
    int base = t * 1024 + tid * 4;
    int v[4];
    #pragma unroll
    for (int k = 0; k < 4; k++) {
        int i = base + k;
        v[k] = (i < NN) ? g_deg[side][i] : 0;
    }
    int tsum = v[0] + v[1] + v[2] + v[3];
    // warp inclusive scan of thread sums
    int x = tsum;
    #pragma unroll
    for (int off = 1; off < 32; off <<= 1) {
        int tt = __shfl_up_sync(0xffffffffu, x, off);
        if (lane >= off) x += tt;
    }
    if (lane == 31) ws[wid] = x;
    // warp 0: reduce tile sums of tiles < t (replaces old k_s2)
    if (wid == 0) {
        int p = 0;
        for (int j = lane; j < t; j += 32) p += g_tilesum[side][j];
        #pragma unroll
        for (int off = 16; off; off >>= 1) p += __shfl_xor_sync(0xffffffffu, p, off);
        if (lane == 0) s_off = p;
    }
    __syncthreads();
    int woff = 0;
    #pragma unroll
    for (int w = 0; w < 7; w++) if (w < wid) woff += ws[w];
    int off = s_off + woff + (x - tsum);   // exclusive offset of this thread's chunk
    #pragma unroll
    for (int k = 0; k < 4; k++) {
        int i = base + k;
        if (i < NN) {
            g_rowptr[side][i] = off;
            g_cursor[side][i] = off;
            g_dinv[side][i]   = rsqrtf((float)(v[k] + 1));  // +1 = self loop
        }
        off += v[k];
    }
    if (t == 0 && tid == 0) g_rowptr[side][NN] = 2 * EE;
}

// fill (atomic-latency-bound) and scale (BW-bound) fused: block-range split so
// the CSR fill's atomic latency hides under the feat-convert's streaming BW.
__global__ void k_fillscale(const int2* __restrict__ esr, const int2* __restrict__ etg,
                            const float4* __restrict__ fsr, const float4* __restrict__ ftg) {
    int b = blockIdx.x;
    if (b < FILL_BLOCKS) {
        int i = b * 256 + threadIdx.x;
        if (i >= 2 * EE) return;
        int side = i >= EE;
        int j = i - side * EE;
        int2 ab = side ? etg[j] : esr[j];
        int p = atomicAdd(&g_cursor[side][ab.x], 1);
        g_adj[side][p] = ab.y;
        int q = atomicAdd(&g_cursor[side][ab.y], 1);
        g_adj[side][q] = ab.x;
    } else {
        // g0 = fp16(feats * dinv[row]); one uint4 (8 halfs) per thread
        int i = (b - FILL_BLOCKS) * 256 + threadIdx.x;   // uint4 index, < 2*NN*32
        int side = i >= NN * 32;
        int j = i - side * NN * 32;
        float s = g_dinv[side][j >> 5];
        const float4* f = side ? ftg : fsr;
        float4 x0 = f[2 * j];
        float4 x1 = f[2 * j + 1];
        uint4 o;
        o.x = f2u(x0.x * s, x0.y * s);
        o.y = f2u(x0.z * s, x0.w * s);
        o.z = f2u(x1.x * s, x1.y * s);
        o.w = f2u(x1.z * s, x1.w * s);
        g_h0[side][j] = o;
    }
}

// ---------------- aggregation: one warp per node, 8 floats / lane --------
// lane l holds float columns [8l .. 8l+7]  (one uint4 = 8 halfs per row)
// FINAL=false: g1[v] = fp16( relu(dinv[v]*acc) * dinv[v] )  -> g_h1
// FINAL=true : row    = l2normalize(dinv[v]*acc)            -> d_out ent region (fp32, stcs)
template <bool FINAL>
__global__ void k_layer(int side, float4* out) {
    int gw = (blockIdx.x * blockDim.x + threadIdx.x) >> 5;
    if (gw >= NN) return;
    int lane = threadIdx.x & 31;

    const uint4* __restrict__ gin = FINAL ? g_h1[side] : g_h0[side];
    float a[8] = {0, 0, 0, 0, 0, 0, 0, 0};
    unpack_add8(a, __ldg(gin + (size_t)gw * 32 + lane));   // self loop

    int s = g_rowptr[side][gw];
    int e = g_rowptr[side][gw + 1];
    const int* __restrict__ adj = g_adj[side];
    for (int base = s; base < e; base += 32) {
        int cnt = min(32, e - base);
        int nb = (lane < cnt) ? __ldg(adj + base + lane) : 0;
        for (int k = 0; k < cnt; k++) {
            int u = __shfl_sync(0xffffffffu, nb, k);
            unpack_add8(a, __ldg(gin + (size_t)u * 32 + lane));
        }
    }

    float dv = g_dinv[side][gw];
    if (!FINAL) {
        float r[8];
        #pragma unroll
        for (int k = 0; k < 8; k++) r[k] = fmaxf(dv * a[k], 0.f) * dv;
        uint4 o;
        o.x = f2u(r[0], r[1]); o.y = f2u(r[2], r[3]);
        o.z = f2u(r[4], r[5]); o.w = f2u(r[6], r[7]);
        g_h1[side][(size_t)gw * 32 + lane] = o;
    } else {
        float r[8];
        float ss = 0.f;
        #pragma unroll
        for (int k = 0; k < 8; k++) { r[k] = dv * a[k]; ss += r[k] * r[k]; }
        #pragma unroll
        for (int off = 16; off; off >>= 1) ss += __shfl_xor_sync(0xffffffffu, ss, off);
        float inv = 1.0f / fmaxf(sqrtf(ss), 1e-12f);
        float4 r0, r1;
        r0.x = r[0] * inv; r0.y = r[1] * inv; r0.z = r[2] * inv; r0.w = r[3] * inv;
        r1.x = r[4] * inv; r1.y = r[5] * inv; r1.z = r[6] * inv; r1.w = r[7] * inv;
        size_t rb = (size_t)(2 * SS) * D4 + (size_t)side * NN * D4 + (size_t)gw * D4;
        __stcs(out + rb + 2 * lane, r0);       // streaming: keep gather table in L2
        __stcs(out + rb + 2 * lane + 1, r1);
    }
}

// seed gather + re-zero g_deg for the next call (graph replays start clean;
// first call starts clean via static zero-initialization)
__global__ void k_seed(const int* __restrict__ ssr, const int* __restrict__ stg,
                       float4* out) {
    int i = blockIdx.x * 256 + threadIdx.x;
    if (i < 2 * NN) ((int*)g_deg)[i] = 0;
    if (i >= 2 * SS * D4) return;
    int row = i >> 6, c = i & 63;
    int side = row >= SS;
    int s = row - side * SS;
    int node = side ? stg[s] : ssr[s];
    size_t src = (size_t)(2 * SS) * D4 + (size_t)side * NN * D4 + (size_t)node * D4 + c;
    out[i] = out[src];
}

// ---------------- launch ----------------
extern "C" void kernel_launch(void* const* d_in, const int* in_sizes, int n_in,
                              void* d_out, int out_size) {
    const float4* fsr = (const float4*)d_in[0];
    const float4* ftg = (const float4*)d_in[1];
    const int2*   esr = (const int2*)d_in[2];
    const int2*   etg = (const int2*)d_in[3];
    const int*    ssr = (const int*)d_in[4];
    const int*    stg = (const int*)d_in[5];
    float4* out = (float4*)d_out;

    k_count<<<(2 * EE + 255) / 256, 256>>>(esr, etg);
    k_s1<<<2 * NT, 256>>>();
    k_s3<<<2 * NT, 256>>>();
    k_fillscale<<<FILL_BLOCKS + SCALE_BLOCKS, 256>>>(esr, etg, fsr, ftg);

    // sides sequential on purpose: keeps each 51 MB fp16 gather table L2-resident
    int lb = (NN * 32 + 255) / 256;   // one warp per node
    k_layer<false><<<lb, 256>>>(0, nullptr);
    k_layer<false><<<lb, 256>>>(1, nullptr);
    k_layer<true><<<lb, 256>>>(0, out);
    k_layer<true><<<lb, 256>>>(1, out);

    k_seed<<<(2 * SS * D4 + 255) / 256, 256>>>(ssr, stg, out);
}